// round 12
// baseline (speedup 1.0000x reference)
#include <cuda_runtime.h>
#include <cuda_fp16.h>

#define MAXN 100000
#define MAXG 512
#define SLOTS 80  // max in-degree slots per dst (Poisson(32): P(deg>=80) ~ 1e-14)

// ---------------- scratch (device globals; zero-initialized at load) ------
__device__ int g_cursor[MAXN];                        // zeroed by gather2 each launch
__device__ __align__(8) float2 g_pair[MAXN * SLOTS];  // (src-as-float-bits, x[src])
__device__ __align__(16) float g_t[MAXN * 8];         // layer-1 output
__device__ __align__(16) __half g_h2[MAXN * 8];       // layer-2 node features (fp16)
__device__ float g_as2[MAXN];                         // src attention logit (L2)
__device__ float g_ad2[MAXN];                         // dst attention logit (L2)
__device__ __align__(16) float g_gsum[MAXG * 8];      // zeroed by final_k each launch
__device__ float g_gcnt[MAXG];                        // zeroed by final_k each launch

__device__ __forceinline__ float lrelu(float z) { return fmaxf(z, 0.2f * z); }

// --- single-pass fixed-stride scatter (ILP=8): one 8B (src,x) store/edge ---
__global__ void __launch_bounds__(256) scatter_k(const int* __restrict__ ei,
                                                 const float* __restrict__ x, int E) {
    int i = (blockIdx.x * blockDim.x + threadIdx.x) * 8;
    if (i + 7 < E) {
        int4 sa = *(const int4*)&ei[i];
        int4 sb = *(const int4*)&ei[i + 4];
        int4 da = *(const int4*)&ei[E + i];
        int4 db = *(const int4*)&ei[E + i + 4];
        float x0 = __ldg(x + sa.x), x1 = __ldg(x + sa.y);
        float x2 = __ldg(x + sa.z), x3 = __ldg(x + sa.w);
        float x4 = __ldg(x + sb.x), x5 = __ldg(x + sb.y);
        float x6 = __ldg(x + sb.z), x7 = __ldg(x + sb.w);
        int p0 = atomicAdd(&g_cursor[da.x], 1);
        int p1 = atomicAdd(&g_cursor[da.y], 1);
        int p2 = atomicAdd(&g_cursor[da.z], 1);
        int p3 = atomicAdd(&g_cursor[da.w], 1);
        int p4 = atomicAdd(&g_cursor[db.x], 1);
        int p5 = atomicAdd(&g_cursor[db.y], 1);
        int p6 = atomicAdd(&g_cursor[db.z], 1);
        int p7 = atomicAdd(&g_cursor[db.w], 1);
        if (p0 < SLOTS) g_pair[da.x * SLOTS + p0] = make_float2(__int_as_float(sa.x), x0);
        if (p1 < SLOTS) g_pair[da.y * SLOTS + p1] = make_float2(__int_as_float(sa.y), x1);
        if (p2 < SLOTS) g_pair[da.z * SLOTS + p2] = make_float2(__int_as_float(sa.z), x2);
        if (p3 < SLOTS) g_pair[da.w * SLOTS + p3] = make_float2(__int_as_float(sa.w), x3);
        if (p4 < SLOTS) g_pair[db.x * SLOTS + p4] = make_float2(__int_as_float(sb.x), x4);
        if (p5 < SLOTS) g_pair[db.y * SLOTS + p5] = make_float2(__int_as_float(sb.y), x5);
        if (p6 < SLOTS) g_pair[db.z * SLOTS + p6] = make_float2(__int_as_float(sb.z), x6);
        if (p7 < SLOTS) g_pair[db.w * SLOTS + p7] = make_float2(__int_as_float(sb.w), x7);
    } else {
        for (int k = i; k < E && k < i + 8; k++) {
            int s = ei[k];
            int d = ei[E + k];
            float xs = __ldg(x + s);
            int p = atomicAdd(&g_cursor[d], 1);
            if (p < SLOTS) g_pair[d * SLOTS + p] = make_float2(__int_as_float(s), xs);
        }
    }
}

// -------- layer 1: 16-lanes-per-dst, fully coalesced; s1/d1 in-block ------
__global__ void __launch_bounds__(256) gather1(const float* __restrict__ x,
                                               const float* __restrict__ W1,
                                               const float* __restrict__ as1,
                                               const float* __restrict__ ad1, int N) {
    __shared__ float ss1[8], sd1[8];
    if (threadIdx.x < 8) {
        int h = threadIdx.x;
        float s = 0.f, d = 0.f;
#pragma unroll
        for (int c = 0; c < 8; c++) {
            float w = __ldg(W1 + h * 8 + c);
            s += w * __ldg(as1 + h * 8 + c);
            d += w * __ldg(ad1 + h * 8 + c);
        }
        ss1[h] = s;
        sd1[h] = d;
    }
    __syncthreads();
    int gid = (blockIdx.x * blockDim.x + threadIdx.x) >> 4;
    int lane = threadIdx.x & 15;
    bool active = gid < N;
    float s1[8], cd[8];
    float xd = 0.f;
    int deg = 0;
    if (active) {
        xd = __ldg(x + gid);
#pragma unroll
        for (int h = 0; h < 8; h++) {
            s1[h] = ss1[h];
            cd[h] = xd * sd1[h];
        }
        deg = min(g_cursor[gid], SLOTS);
    }
    int beg = gid * SLOTS;
    float den[8] = {0, 0, 0, 0, 0, 0, 0, 0};
    float num[8] = {0, 0, 0, 0, 0, 0, 0, 0};
    int k = lane;
    for (; k + 16 < deg; k += 32) {
        float xs0 = __ldg(&g_pair[beg + k]).y;
        float xs1 = __ldg(&g_pair[beg + k + 16]).y;
#pragma unroll
        for (int h = 0; h < 8; h++) {
            float w0 = __expf(lrelu(fmaf(xs0, s1[h], cd[h])));
            float w1 = __expf(lrelu(fmaf(xs1, s1[h], cd[h])));
            den[h] += w0 + w1;
            num[h] = fmaf(w0, xs0, fmaf(w1, xs1, num[h]));
        }
    }
    if (k < deg) {
        float xs = __ldg(&g_pair[beg + k]).y;
#pragma unroll
        for (int h = 0; h < 8; h++) {
            float w = __expf(lrelu(fmaf(xs, s1[h], cd[h])));
            den[h] += w;
            num[h] = fmaf(w, xs, num[h]);
        }
    }
#pragma unroll
    for (int o = 8; o > 0; o >>= 1) {
#pragma unroll
        for (int h = 0; h < 8; h++) {
            den[h] += __shfl_xor_sync(0xffffffffu, den[h], o);
            num[h] += __shfl_xor_sync(0xffffffffu, num[h], o);
        }
    }
    if (active && lane == 0) {
        float t[8];
#pragma unroll
        for (int h = 0; h < 8; h++) {
            float w = __expf(lrelu(fmaf(xd, s1[h], cd[h])));  // self-loop
            t[h] = (num[h] + w * xd) / (den[h] + w + 1e-16f);
        }
        *(float4*)&g_t[gid * 8]     = make_float4(t[0], t[1], t[2], t[3]);
        *(float4*)&g_t[gid * 8 + 4] = make_float4(t[4], t[5], t[6], t[7]);
    }
}

// ------- node MLP: elu(t*W1+b1) @ W2 -> h2 (fp16), as2, ad2 --------------
__global__ void __launch_bounds__(256) node1(
        const float* __restrict__ W1, const float* __restrict__ b1,
        const float* __restrict__ W2,
        const float* __restrict__ as2w, const float* __restrict__ ad2w, int N) {
    __shared__ float sW1[64], sb1[64], sW2[512], sas[8], sad[8];
    int t = threadIdx.x;
    if (t < 64) { sW1[t] = W1[t]; sb1[t] = b1[t]; }
    for (int k = t; k < 512; k += blockDim.x) sW2[k] = W2[k];
    if (t < 8) { sas[t] = as2w[t]; sad[t] = ad2w[t]; }
    __syncthreads();

    int n = blockIdx.x * blockDim.x + t;
    if (n >= N) return;
    float4 t0 = *(const float4*)&g_t[n * 8];
    float4 t1 = *(const float4*)&g_t[n * 8 + 4];
    float tv[8] = {t0.x, t0.y, t0.z, t0.w, t1.x, t1.y, t1.z, t1.w};
    float acc[8];
#pragma unroll
    for (int c = 0; c < 8; c++) acc[c] = 0.f;
#pragma unroll
    for (int k = 0; k < 64; k++) {
        float v = fmaf(tv[k >> 3], sW1[k], sb1[k]);
        v = v > 0.f ? v : (__expf(v) - 1.f);  // ELU
#pragma unroll
        for (int c = 0; c < 8; c++) acc[c] = fmaf(v, sW2[k * 8 + c], acc[c]);
    }
    float as = 0.f, ad = 0.f;
#pragma unroll
    for (int c = 0; c < 8; c++) {
        as = fmaf(acc[c], sas[c], as);
        ad = fmaf(acc[c], sad[c], ad);
    }
    __half2 h01 = __floats2half2_rn(acc[0], acc[1]);
    __half2 h23 = __floats2half2_rn(acc[2], acc[3]);
    __half2 h45 = __floats2half2_rn(acc[4], acc[5]);
    __half2 h67 = __floats2half2_rn(acc[6], acc[7]);
    *(uint4*)&g_h2[n * 8] = make_uint4(*(unsigned*)&h01, *(unsigned*)&h23,
                                       *(unsigned*)&h45, *(unsigned*)&h67);
    g_as2[n] = as;
    g_ad2[n] = ad;
}

// --- layer 2: 8-lanes-per-dst, batched loads, sequential unpack (low-reg) --
__global__ void __launch_bounds__(256, 5) gather2(const int* __restrict__ batch,
                                                  const float* __restrict__ b2,
                                                  const float* __restrict__ as2w, int N) {
    int gid = (blockIdx.x * blockDim.x + threadIdx.x) >> 3;
    int lane = threadIdx.x & 7;
    bool active = gid < N;
    float att[8];
#pragma unroll
    for (int c = 0; c < 8; c++) att[c] = __ldg(as2w + c);
    float ad = 0.f;
    int deg = 0;
    if (active) {
        ad = g_ad2[gid];
        deg = min(g_cursor[gid], SLOTS);
    }
    int beg = gid * SLOTS;
    float acc[8] = {0, 0, 0, 0, 0, 0, 0, 0};
    float den = 0.f;
    for (int k = 0; k < deg; k += 32) {
        // ---- batched independent loads (MLP) ----
        uint4 r[4];
        bool valid[4];
#pragma unroll
        for (int j = 0; j < 4; j++) {
            int idx = k + lane + j * 8;
            valid[j] = idx < deg;
            int ci = min(idx, SLOTS - 1);
            int s = valid[j] ? __float_as_int(__ldg(&g_pair[beg + ci]).x) : 0;
            r[j] = __ldg((const uint4*)&g_h2[s * 8]);
        }
        // ---- sequential unpack/dot/accumulate (one row live at a time) ----
#pragma unroll
        for (int j = 0; j < 4; j++) {
            float2 fa = __half22float2(*(__half2*)&r[j].x);
            float2 fb = __half22float2(*(__half2*)&r[j].y);
            float2 fc = __half22float2(*(__half2*)&r[j].z);
            float2 fd = __half22float2(*(__half2*)&r[j].w);
            float dot = fa.x * att[0];
            dot = fmaf(fa.y, att[1], dot);
            dot = fmaf(fb.x, att[2], dot);
            dot = fmaf(fb.y, att[3], dot);
            dot = fmaf(fc.x, att[4], dot);
            dot = fmaf(fc.y, att[5], dot);
            dot = fmaf(fd.x, att[6], dot);
            dot = fmaf(fd.y, att[7], dot);
            float w = valid[j] ? __expf(lrelu(dot + ad)) : 0.f;
            acc[0] = fmaf(w, fa.x, acc[0]);
            acc[1] = fmaf(w, fa.y, acc[1]);
            acc[2] = fmaf(w, fb.x, acc[2]);
            acc[3] = fmaf(w, fb.y, acc[3]);
            acc[4] = fmaf(w, fc.x, acc[4]);
            acc[5] = fmaf(w, fc.y, acc[5]);
            acc[6] = fmaf(w, fd.x, acc[6]);
            acc[7] = fmaf(w, fd.y, acc[7]);
            den += w;
        }
    }
#pragma unroll
    for (int o = 4; o > 0; o >>= 1) {
#pragma unroll
        for (int c = 0; c < 8; c++) acc[c] += __shfl_xor_sync(0xffffffffu, acc[c], o);
        den += __shfl_xor_sync(0xffffffffu, den, o);
    }
    if (active && lane == 0) {
        g_cursor[gid] = 0;  // restore launch invariant for next call's scatter
        uint4 rh = *(const uint4*)&g_h2[gid * 8];
        float2 ha = __half22float2(*(__half2*)&rh.x);
        float2 hb = __half22float2(*(__half2*)&rh.y);
        float2 hc = __half22float2(*(__half2*)&rh.z);
        float2 hd2 = __half22float2(*(__half2*)&rh.w);
        float hd[8] = {ha.x, ha.y, hb.x, hb.y, hc.x, hc.y, hd2.x, hd2.y};
        float w = __expf(lrelu(g_as2[gid] + ad));  // self-loop
        float inv = 1.f / (den + w + 1e-16f);
        float o[8];
#pragma unroll
        for (int c = 0; c < 8; c++)
            o[c] = fmaf(acc[c] + w * hd[c], inv, b2[c]);
        int b = batch[gid];
        atomicAdd((float4*)&g_gsum[b * 8], make_float4(o[0], o[1], o[2], o[3]));
        atomicAdd((float4*)&g_gsum[b * 8 + 4], make_float4(o[4], o[5], o[6], o[7]));
        atomicAdd(&g_gcnt[b], 1.f);
    }
}

// -------- pooled -> linear -> log_softmax (re-zeroes pool buffers) --------
__global__ void final_k(const float* __restrict__ lw, const float* __restrict__ lb,
                        float* __restrict__ out, int G) {
    int g = blockIdx.x * blockDim.x + threadIdx.x;
    if (g >= G) return;
    float inv = 1.f / fmaxf(g_gcnt[g], 1.f);
    float p[8];
#pragma unroll
    for (int c = 0; c < 8; c++) p[c] = g_gsum[g * 8 + c] * inv;
    // restore launch invariant for next call's gather2
    *(float4*)&g_gsum[g * 8]     = make_float4(0.f, 0.f, 0.f, 0.f);
    *(float4*)&g_gsum[g * 8 + 4] = make_float4(0.f, 0.f, 0.f, 0.f);
    g_gcnt[g] = 0.f;
    float l[10];
    float m = -1e30f;
#pragma unroll
    for (int o = 0; o < 10; o++) {
        float a = lb[o];
#pragma unroll
        for (int c = 0; c < 8; c++) a = fmaf(p[c], lw[c * 10 + o], a);
        l[o] = a;
        m = fmaxf(m, a);
    }
    float s = 0.f;
#pragma unroll
    for (int o = 0; o < 10; o++) s += expf(l[o] - m);
    float lse = m + logf(s);
#pragma unroll
    for (int o = 0; o < 10; o++) out[g * 10 + o] = l[o] - lse;
}

// ---------------- launch ----------------
extern "C" void kernel_launch(void* const* d_in, const int* in_sizes, int n_in,
                              void* d_out, int out_size) {
    const float* x   = (const float*)d_in[0];
    const int*   ei  = (const int*)d_in[1];
    const int*   bat = (const int*)d_in[2];
    const float* W1  = (const float*)d_in[4];
    const float* as1 = (const float*)d_in[5];
    const float* ad1 = (const float*)d_in[6];
    const float* b1  = (const float*)d_in[7];
    const float* W2  = (const float*)d_in[8];
    const float* as2 = (const float*)d_in[9];
    const float* ad2 = (const float*)d_in[10];
    const float* b2  = (const float*)d_in[11];
    const float* lw  = (const float*)d_in[12];
    const float* lb  = (const float*)d_in[13];

    int N = in_sizes[0];
    int E = in_sizes[1] / 2;
    int G = out_size / 10;
    float* out = (float*)d_out;

    scatter_k<<<(E / 8 + 255) / 256, 256>>>(ei, x, E);            // idx 0
    gather1<<<(N * 16 + 255) / 256, 256>>>(x, W1, as1, ad1, N);   // idx 1
    node1<<<(N + 255) / 256, 256>>>(W1, b1, W2, as2, ad2, N);     // idx 2
    gather2<<<(N * 8 + 255) / 256, 256>>>(bat, b2, as2, N);       // idx 3 (profiled)
    final_k<<<(G + 127) / 128, 128>>>(lw, lb, out, G);            // idx 4
}

// round 13
// speedup vs baseline: 1.0322x; 1.0322x over previous
#include <cuda_runtime.h>
#include <cuda_fp16.h>

#define MAXN 100000
#define MAXG 512
#define SLOTS 80  // max in-degree slots per dst (Poisson(32): P(deg>=80) ~ 1e-14)

// ---------------- scratch (device globals; zero-initialized at load) ------
__device__ int g_cursor[MAXN];                        // zeroed by gather2 each launch
__device__ __align__(8) float2 g_pair[MAXN * SLOTS];  // (src-as-float-bits, x[src])
__device__ __align__(16) float g_t[MAXN * 8];         // layer-1 output
__device__ __align__(16) __half g_h2[MAXN * 8];       // layer-2 node features (fp16)
__device__ float g_as2[MAXN];                         // src attention logit (L2)
__device__ float g_ad2[MAXN];                         // dst attention logit (L2)
__device__ __align__(16) float g_gsum[MAXG * 8];      // zeroed by final_k each launch
__device__ float g_gcnt[MAXG];                        // zeroed by final_k each launch

__device__ __forceinline__ float lrelu(float z) { return fmaxf(z, 0.2f * z); }

// --- single-pass fixed-stride scatter (ILP=8): one 8B (src,x) store/edge ---
__global__ void __launch_bounds__(256) scatter_k(const int* __restrict__ ei,
                                                 const float* __restrict__ x, int E) {
    int i = (blockIdx.x * blockDim.x + threadIdx.x) * 8;
    if (i + 7 < E) {
        int4 sa = *(const int4*)&ei[i];
        int4 sb = *(const int4*)&ei[i + 4];
        int4 da = *(const int4*)&ei[E + i];
        int4 db = *(const int4*)&ei[E + i + 4];
        float x0 = __ldg(x + sa.x), x1 = __ldg(x + sa.y);
        float x2 = __ldg(x + sa.z), x3 = __ldg(x + sa.w);
        float x4 = __ldg(x + sb.x), x5 = __ldg(x + sb.y);
        float x6 = __ldg(x + sb.z), x7 = __ldg(x + sb.w);
        int p0 = atomicAdd(&g_cursor[da.x], 1);
        int p1 = atomicAdd(&g_cursor[da.y], 1);
        int p2 = atomicAdd(&g_cursor[da.z], 1);
        int p3 = atomicAdd(&g_cursor[da.w], 1);
        int p4 = atomicAdd(&g_cursor[db.x], 1);
        int p5 = atomicAdd(&g_cursor[db.y], 1);
        int p6 = atomicAdd(&g_cursor[db.z], 1);
        int p7 = atomicAdd(&g_cursor[db.w], 1);
        if (p0 < SLOTS) g_pair[da.x * SLOTS + p0] = make_float2(__int_as_float(sa.x), x0);
        if (p1 < SLOTS) g_pair[da.y * SLOTS + p1] = make_float2(__int_as_float(sa.y), x1);
        if (p2 < SLOTS) g_pair[da.z * SLOTS + p2] = make_float2(__int_as_float(sa.z), x2);
        if (p3 < SLOTS) g_pair[da.w * SLOTS + p3] = make_float2(__int_as_float(sa.w), x3);
        if (p4 < SLOTS) g_pair[db.x * SLOTS + p4] = make_float2(__int_as_float(sb.x), x4);
        if (p5 < SLOTS) g_pair[db.y * SLOTS + p5] = make_float2(__int_as_float(sb.y), x5);
        if (p6 < SLOTS) g_pair[db.z * SLOTS + p6] = make_float2(__int_as_float(sb.z), x6);
        if (p7 < SLOTS) g_pair[db.w * SLOTS + p7] = make_float2(__int_as_float(sb.w), x7);
    } else {
        for (int k = i; k < E && k < i + 8; k++) {
            int s = ei[k];
            int d = ei[E + k];
            float xs = __ldg(x + s);
            int p = atomicAdd(&g_cursor[d], 1);
            if (p < SLOTS) g_pair[d * SLOTS + p] = make_float2(__int_as_float(s), xs);
        }
    }
}

// -------- layer 1: 16-lanes-per-dst, fully coalesced; s1/d1 in-block ------
__global__ void __launch_bounds__(256) gather1(const float* __restrict__ x,
                                               const float* __restrict__ W1,
                                               const float* __restrict__ as1,
                                               const float* __restrict__ ad1, int N) {
    __shared__ float ss1[8], sd1[8];
    if (threadIdx.x < 8) {
        int h = threadIdx.x;
        float s = 0.f, d = 0.f;
#pragma unroll
        for (int c = 0; c < 8; c++) {
            float w = __ldg(W1 + h * 8 + c);
            s += w * __ldg(as1 + h * 8 + c);
            d += w * __ldg(ad1 + h * 8 + c);
        }
        ss1[h] = s;
        sd1[h] = d;
    }
    __syncthreads();
    int gid = (blockIdx.x * blockDim.x + threadIdx.x) >> 4;
    int lane = threadIdx.x & 15;
    bool active = gid < N;
    float s1[8], cd[8];
    float xd = 0.f;
    int deg = 0;
    if (active) {
        xd = __ldg(x + gid);
#pragma unroll
        for (int h = 0; h < 8; h++) {
            s1[h] = ss1[h];
            cd[h] = xd * sd1[h];
        }
        deg = min(g_cursor[gid], SLOTS);
    }
    int beg = gid * SLOTS;
    float den[8] = {0, 0, 0, 0, 0, 0, 0, 0};
    float num[8] = {0, 0, 0, 0, 0, 0, 0, 0};
    int k = lane;
    for (; k + 16 < deg; k += 32) {
        float xs0 = __ldg(&g_pair[beg + k]).y;
        float xs1 = __ldg(&g_pair[beg + k + 16]).y;
#pragma unroll
        for (int h = 0; h < 8; h++) {
            float w0 = __expf(lrelu(fmaf(xs0, s1[h], cd[h])));
            float w1 = __expf(lrelu(fmaf(xs1, s1[h], cd[h])));
            den[h] += w0 + w1;
            num[h] = fmaf(w0, xs0, fmaf(w1, xs1, num[h]));
        }
    }
    if (k < deg) {
        float xs = __ldg(&g_pair[beg + k]).y;
#pragma unroll
        for (int h = 0; h < 8; h++) {
            float w = __expf(lrelu(fmaf(xs, s1[h], cd[h])));
            den[h] += w;
            num[h] = fmaf(w, xs, num[h]);
        }
    }
#pragma unroll
    for (int o = 8; o > 0; o >>= 1) {
#pragma unroll
        for (int h = 0; h < 8; h++) {
            den[h] += __shfl_xor_sync(0xffffffffu, den[h], o);
            num[h] += __shfl_xor_sync(0xffffffffu, num[h], o);
        }
    }
    if (active && lane == 0) {
        float t[8];
#pragma unroll
        for (int h = 0; h < 8; h++) {
            float w = __expf(lrelu(fmaf(xd, s1[h], cd[h])));  // self-loop
            t[h] = (num[h] + w * xd) / (den[h] + w + 1e-16f);
        }
        *(float4*)&g_t[gid * 8]     = make_float4(t[0], t[1], t[2], t[3]);
        *(float4*)&g_t[gid * 8 + 4] = make_float4(t[4], t[5], t[6], t[7]);
    }
}

// ------- node MLP: elu(t*W1+b1) @ W2 -> h2 (fp16), as2, ad2 --------------
__global__ void __launch_bounds__(256) node1(
        const float* __restrict__ W1, const float* __restrict__ b1,
        const float* __restrict__ W2,
        const float* __restrict__ as2w, const float* __restrict__ ad2w, int N) {
    __shared__ float sW1[64], sb1[64], sW2[512], sas[8], sad[8];
    int t = threadIdx.x;
    if (t < 64) { sW1[t] = W1[t]; sb1[t] = b1[t]; }
    for (int k = t; k < 512; k += blockDim.x) sW2[k] = W2[k];
    if (t < 8) { sas[t] = as2w[t]; sad[t] = ad2w[t]; }
    __syncthreads();

    int n = blockIdx.x * blockDim.x + t;
    if (n >= N) return;
    float4 t0 = *(const float4*)&g_t[n * 8];
    float4 t1 = *(const float4*)&g_t[n * 8 + 4];
    float tv[8] = {t0.x, t0.y, t0.z, t0.w, t1.x, t1.y, t1.z, t1.w};
    float acc[8];
#pragma unroll
    for (int c = 0; c < 8; c++) acc[c] = 0.f;
#pragma unroll
    for (int k = 0; k < 64; k++) {
        float v = fmaf(tv[k >> 3], sW1[k], sb1[k]);
        v = v > 0.f ? v : (__expf(v) - 1.f);  // ELU
#pragma unroll
        for (int c = 0; c < 8; c++) acc[c] = fmaf(v, sW2[k * 8 + c], acc[c]);
    }
    float as = 0.f, ad = 0.f;
#pragma unroll
    for (int c = 0; c < 8; c++) {
        as = fmaf(acc[c], sas[c], as);
        ad = fmaf(acc[c], sad[c], ad);
    }
    __half2 h01 = __floats2half2_rn(acc[0], acc[1]);
    __half2 h23 = __floats2half2_rn(acc[2], acc[3]);
    __half2 h45 = __floats2half2_rn(acc[4], acc[5]);
    __half2 h67 = __floats2half2_rn(acc[6], acc[7]);
    *(uint4*)&g_h2[n * 8] = make_uint4(*(unsigned*)&h01, *(unsigned*)&h23,
                                       *(unsigned*)&h45, *(unsigned*)&h67);
    g_as2[n] = as;
    g_ad2[n] = ad;
}

// --- layer 2: 8-lanes-per-dst, batched loads, smem consts, 6 blocks/SM ----
__global__ void __launch_bounds__(256, 6) gather2(const int* __restrict__ batch,
                                                  const float* __restrict__ b2,
                                                  const float* __restrict__ as2w, int N) {
    __shared__ float satt[8], sb2[8];
    if (threadIdx.x < 8) {
        satt[threadIdx.x] = __ldg(as2w + threadIdx.x);
        sb2[threadIdx.x] = __ldg(b2 + threadIdx.x);
    }
    __syncthreads();
    int gid = (blockIdx.x * blockDim.x + threadIdx.x) >> 3;
    int lane = threadIdx.x & 7;
    bool active = gid < N;
    float ad = 0.f;
    int deg = 0;
    if (active) {
        ad = g_ad2[gid];
        deg = min(g_cursor[gid], SLOTS);
    }
    int beg = gid * SLOTS;
    float acc[8] = {0, 0, 0, 0, 0, 0, 0, 0};
    float den = 0.f;
    for (int k = 0; k < deg; k += 32) {
        // ---- batched independent loads (MLP) ----
        uint4 r[4];
        bool valid[4];
#pragma unroll
        for (int j = 0; j < 4; j++) {
            int idx = k + lane + j * 8;
            valid[j] = idx < deg;
            int ci = min(idx, SLOTS - 1);
            int s = valid[j] ? __float_as_int(__ldg(&g_pair[beg + ci]).x) : 0;
            r[j] = __ldg((const uint4*)&g_h2[s * 8]);
        }
        // ---- sequential unpack/dot/accumulate (one row live at a time) ----
#pragma unroll
        for (int j = 0; j < 4; j++) {
            float2 fa = __half22float2(*(__half2*)&r[j].x);
            float2 fb = __half22float2(*(__half2*)&r[j].y);
            float2 fc = __half22float2(*(__half2*)&r[j].z);
            float2 fd = __half22float2(*(__half2*)&r[j].w);
            float dot = fa.x * satt[0];
            dot = fmaf(fa.y, satt[1], dot);
            dot = fmaf(fb.x, satt[2], dot);
            dot = fmaf(fb.y, satt[3], dot);
            dot = fmaf(fc.x, satt[4], dot);
            dot = fmaf(fc.y, satt[5], dot);
            dot = fmaf(fd.x, satt[6], dot);
            dot = fmaf(fd.y, satt[7], dot);
            float w = valid[j] ? __expf(lrelu(dot + ad)) : 0.f;
            acc[0] = fmaf(w, fa.x, acc[0]);
            acc[1] = fmaf(w, fa.y, acc[1]);
            acc[2] = fmaf(w, fb.x, acc[2]);
            acc[3] = fmaf(w, fb.y, acc[3]);
            acc[4] = fmaf(w, fc.x, acc[4]);
            acc[5] = fmaf(w, fc.y, acc[5]);
            acc[6] = fmaf(w, fd.x, acc[6]);
            acc[7] = fmaf(w, fd.y, acc[7]);
            den += w;
        }
    }
#pragma unroll
    for (int o = 4; o > 0; o >>= 1) {
#pragma unroll
        for (int c = 0; c < 8; c++) acc[c] += __shfl_xor_sync(0xffffffffu, acc[c], o);
        den += __shfl_xor_sync(0xffffffffu, den, o);
    }
    if (active && lane == 0) {
        g_cursor[gid] = 0;  // restore launch invariant for next call's scatter
        uint4 rh = *(const uint4*)&g_h2[gid * 8];
        float2 ha = __half22float2(*(__half2*)&rh.x);
        float2 hb = __half22float2(*(__half2*)&rh.y);
        float2 hc = __half22float2(*(__half2*)&rh.z);
        float2 hd2 = __half22float2(*(__half2*)&rh.w);
        float hd[8] = {ha.x, ha.y, hb.x, hb.y, hc.x, hc.y, hd2.x, hd2.y};
        float w = __expf(lrelu(g_as2[gid] + ad));  // self-loop
        float inv = 1.f / (den + w + 1e-16f);
        float o[8];
#pragma unroll
        for (int c = 0; c < 8; c++)
            o[c] = fmaf(acc[c] + w * hd[c], inv, sb2[c]);
        int b = batch[gid];
        atomicAdd((float4*)&g_gsum[b * 8], make_float4(o[0], o[1], o[2], o[3]));
        atomicAdd((float4*)&g_gsum[b * 8 + 4], make_float4(o[4], o[5], o[6], o[7]));
        atomicAdd(&g_gcnt[b], 1.f);
    }
}

// -------- pooled -> linear -> log_softmax (re-zeroes pool buffers) --------
__global__ void final_k(const float* __restrict__ lw, const float* __restrict__ lb,
                        float* __restrict__ out, int G) {
    int g = blockIdx.x * blockDim.x + threadIdx.x;
    if (g >= G) return;
    float inv = 1.f / fmaxf(g_gcnt[g], 1.f);
    float p[8];
#pragma unroll
    for (int c = 0; c < 8; c++) p[c] = g_gsum[g * 8 + c] * inv;
    // restore launch invariant for next call's gather2
    *(float4*)&g_gsum[g * 8]     = make_float4(0.f, 0.f, 0.f, 0.f);
    *(float4*)&g_gsum[g * 8 + 4] = make_float4(0.f, 0.f, 0.f, 0.f);
    g_gcnt[g] = 0.f;
    float l[10];
    float m = -1e30f;
#pragma unroll
    for (int o = 0; o < 10; o++) {
        float a = lb[o];
#pragma unroll
        for (int c = 0; c < 8; c++) a = fmaf(p[c], lw[c * 10 + o], a);
        l[o] = a;
        m = fmaxf(m, a);
    }
    float s = 0.f;
#pragma unroll
    for (int o = 0; o < 10; o++) s += expf(l[o] - m);
    float lse = m + logf(s);
#pragma unroll
    for (int o = 0; o < 10; o++) out[g * 10 + o] = l[o] - lse;
}

// ---------------- launch ----------------
extern "C" void kernel_launch(void* const* d_in, const int* in_sizes, int n_in,
                              void* d_out, int out_size) {
    const float* x   = (const float*)d_in[0];
    const int*   ei  = (const int*)d_in[1];
    const int*   bat = (const int*)d_in[2];
    const float* W1  = (const float*)d_in[4];
    const float* as1 = (const float*)d_in[5];
    const float* ad1 = (const float*)d_in[6];
    const float* b1  = (const float*)d_in[7];
    const float* W2  = (const float*)d_in[8];
    const float* as2 = (const float*)d_in[9];
    const float* ad2 = (const float*)d_in[10];
    const float* b2  = (const float*)d_in[11];
    const float* lw  = (const float*)d_in[12];
    const float* lb  = (const float*)d_in[13];

    int N = in_sizes[0];
    int E = in_sizes[1] / 2;
    int G = out_size / 10;
    float* out = (float*)d_out;

    scatter_k<<<(E / 8 + 255) / 256, 256>>>(ei, x, E);            // idx 0
    gather1<<<(N * 16 + 255) / 256, 256>>>(x, W1, as1, ad1, N);   // idx 1
    node1<<<(N + 255) / 256, 256>>>(W1, b1, W2, as2, ad2, N);     // idx 2
    gather2<<<(N * 8 + 255) / 256, 256>>>(bat, b2, as2, N);       // idx 3 (profiled)
    final_k<<<(G + 127) / 128, 128>>>(lw, lb, out, G);            // idx 4
}

// round 14
// speedup vs baseline: 1.0394x; 1.0070x over previous
#include <cuda_runtime.h>
#include <cuda_fp16.h>

#define MAXN 100000
#define MAXG 512
#define SLOTS 80  // max in-degree slots per dst (Poisson(32): P(deg>=80) ~ 1e-14)

// ---------------- scratch (device globals; zero-initialized at load) ------
__device__ int g_cursor[MAXN];                        // zeroed by gather2 each launch
__device__ __align__(8) float2 g_pair[MAXN * SLOTS];  // (src-as-float-bits, x[src])
__device__ __align__(16) float g_t[MAXN * 8];         // layer-1 output
__device__ __align__(16) __half g_h2[MAXN * 8];       // layer-2 node features (fp16)
__device__ float g_as2[MAXN];                         // src attention logit (L2)
__device__ float g_ad2[MAXN];                         // dst attention logit (L2)
__device__ __align__(16) float g_gsum[MAXG * 8];      // zeroed by final_k each launch
__device__ float g_gcnt[MAXG];                        // zeroed by final_k each launch

__device__ __forceinline__ float lrelu(float z) { return fmaxf(z, 0.2f * z); }

// -- single-pass fixed-stride scatter (ILP=16): one 8B (src,x) store/edge --
__global__ void __launch_bounds__(256) scatter_k(const int* __restrict__ ei,
                                                 const float* __restrict__ x, int E) {
    int i = (blockIdx.x * blockDim.x + threadIdx.x) * 16;
    if (i + 15 < E) {
        int s[16], d[16];
#pragma unroll
        for (int j = 0; j < 4; j++) {
            int4 sv = *(const int4*)&ei[i + j * 4];
            int4 dv = *(const int4*)&ei[E + i + j * 4];
            s[j * 4 + 0] = sv.x; s[j * 4 + 1] = sv.y;
            s[j * 4 + 2] = sv.z; s[j * 4 + 3] = sv.w;
            d[j * 4 + 0] = dv.x; d[j * 4 + 1] = dv.y;
            d[j * 4 + 2] = dv.z; d[j * 4 + 3] = dv.w;
        }
        float xv[16];
#pragma unroll
        for (int j = 0; j < 16; j++) xv[j] = __ldg(x + s[j]);   // independent
        int p[16];
#pragma unroll
        for (int j = 0; j < 16; j++) p[j] = atomicAdd(&g_cursor[d[j]], 1);  // independent
#pragma unroll
        for (int j = 0; j < 16; j++)
            if (p[j] < SLOTS)
                g_pair[d[j] * SLOTS + p[j]] = make_float2(__int_as_float(s[j]), xv[j]);
    } else {
        for (int k = i; k < E && k < i + 16; k++) {
            int s = ei[k];
            int d = ei[E + k];
            float xs = __ldg(x + s);
            int p = atomicAdd(&g_cursor[d], 1);
            if (p < SLOTS) g_pair[d * SLOTS + p] = make_float2(__int_as_float(s), xs);
        }
    }
}

// -------- layer 1: 16-lanes-per-dst, fully coalesced; s1/d1 in-block ------
__global__ void __launch_bounds__(256) gather1(const float* __restrict__ x,
                                               const float* __restrict__ W1,
                                               const float* __restrict__ as1,
                                               const float* __restrict__ ad1, int N) {
    __shared__ float ss1[8], sd1[8];
    if (threadIdx.x < 8) {
        int h = threadIdx.x;
        float s = 0.f, d = 0.f;
#pragma unroll
        for (int c = 0; c < 8; c++) {
            float w = __ldg(W1 + h * 8 + c);
            s += w * __ldg(as1 + h * 8 + c);
            d += w * __ldg(ad1 + h * 8 + c);
        }
        ss1[h] = s;
        sd1[h] = d;
    }
    __syncthreads();
    int gid = (blockIdx.x * blockDim.x + threadIdx.x) >> 4;
    int lane = threadIdx.x & 15;
    bool active = gid < N;
    float s1[8], cd[8];
    float xd = 0.f;
    int deg = 0;
    if (active) {
        xd = __ldg(x + gid);
#pragma unroll
        for (int h = 0; h < 8; h++) {
            s1[h] = ss1[h];
            cd[h] = xd * sd1[h];
        }
        deg = min(g_cursor[gid], SLOTS);
    }
    int beg = gid * SLOTS;
    float den[8] = {0, 0, 0, 0, 0, 0, 0, 0};
    float num[8] = {0, 0, 0, 0, 0, 0, 0, 0};
    int k = lane;
    for (; k + 16 < deg; k += 32) {
        float xs0 = __ldg(&g_pair[beg + k]).y;
        float xs1 = __ldg(&g_pair[beg + k + 16]).y;
#pragma unroll
        for (int h = 0; h < 8; h++) {
            float w0 = __expf(lrelu(fmaf(xs0, s1[h], cd[h])));
            float w1 = __expf(lrelu(fmaf(xs1, s1[h], cd[h])));
            den[h] += w0 + w1;
            num[h] = fmaf(w0, xs0, fmaf(w1, xs1, num[h]));
        }
    }
    if (k < deg) {
        float xs = __ldg(&g_pair[beg + k]).y;
#pragma unroll
        for (int h = 0; h < 8; h++) {
            float w = __expf(lrelu(fmaf(xs, s1[h], cd[h])));
            den[h] += w;
            num[h] = fmaf(w, xs, num[h]);
        }
    }
#pragma unroll
    for (int o = 8; o > 0; o >>= 1) {
#pragma unroll
        for (int h = 0; h < 8; h++) {
            den[h] += __shfl_xor_sync(0xffffffffu, den[h], o);
            num[h] += __shfl_xor_sync(0xffffffffu, num[h], o);
        }
    }
    if (active && lane == 0) {
        float t[8];
#pragma unroll
        for (int h = 0; h < 8; h++) {
            float w = __expf(lrelu(fmaf(xd, s1[h], cd[h])));  // self-loop
            t[h] = (num[h] + w * xd) / (den[h] + w + 1e-16f);
        }
        *(float4*)&g_t[gid * 8]     = make_float4(t[0], t[1], t[2], t[3]);
        *(float4*)&g_t[gid * 8 + 4] = make_float4(t[4], t[5], t[6], t[7]);
    }
}

// ------- node MLP: elu(t*W1+b1) @ W2 -> h2 (fp16), as2, ad2 --------------
__global__ void __launch_bounds__(256) node1(
        const float* __restrict__ W1, const float* __restrict__ b1,
        const float* __restrict__ W2,
        const float* __restrict__ as2w, const float* __restrict__ ad2w, int N) {
    __shared__ float sW1[64], sb1[64], sW2[512], sas[8], sad[8];
    int t = threadIdx.x;
    if (t < 64) { sW1[t] = W1[t]; sb1[t] = b1[t]; }
    for (int k = t; k < 512; k += blockDim.x) sW2[k] = W2[k];
    if (t < 8) { sas[t] = as2w[t]; sad[t] = ad2w[t]; }
    __syncthreads();

    int n = blockIdx.x * blockDim.x + t;
    if (n >= N) return;
    float4 t0 = *(const float4*)&g_t[n * 8];
    float4 t1 = *(const float4*)&g_t[n * 8 + 4];
    float tv[8] = {t0.x, t0.y, t0.z, t0.w, t1.x, t1.y, t1.z, t1.w};
    float acc[8];
#pragma unroll
    for (int c = 0; c < 8; c++) acc[c] = 0.f;
#pragma unroll
    for (int k = 0; k < 64; k++) {
        float v = fmaf(tv[k >> 3], sW1[k], sb1[k]);
        v = v > 0.f ? v : (__expf(v) - 1.f);  // ELU
#pragma unroll
        for (int c = 0; c < 8; c++) acc[c] = fmaf(v, sW2[k * 8 + c], acc[c]);
    }
    float as = 0.f, ad = 0.f;
#pragma unroll
    for (int c = 0; c < 8; c++) {
        as = fmaf(acc[c], sas[c], as);
        ad = fmaf(acc[c], sad[c], ad);
    }
    __half2 h01 = __floats2half2_rn(acc[0], acc[1]);
    __half2 h23 = __floats2half2_rn(acc[2], acc[3]);
    __half2 h45 = __floats2half2_rn(acc[4], acc[5]);
    __half2 h67 = __floats2half2_rn(acc[6], acc[7]);
    *(uint4*)&g_h2[n * 8] = make_uint4(*(unsigned*)&h01, *(unsigned*)&h23,
                                       *(unsigned*)&h45, *(unsigned*)&h67);
    g_as2[n] = as;
    g_ad2[n] = ad;
}

// --- layer 2 (R12 best config): 8-lanes-per-dst, batched loads, 5 blk/SM --
__global__ void __launch_bounds__(256, 5) gather2(const int* __restrict__ batch,
                                                  const float* __restrict__ b2,
                                                  const float* __restrict__ as2w, int N) {
    int gid = (blockIdx.x * blockDim.x + threadIdx.x) >> 3;
    int lane = threadIdx.x & 7;
    bool active = gid < N;
    float att[8];
#pragma unroll
    for (int c = 0; c < 8; c++) att[c] = __ldg(as2w + c);
    float ad = 0.f;
    int deg = 0;
    if (active) {
        ad = g_ad2[gid];
        deg = min(g_cursor[gid], SLOTS);
    }
    int beg = gid * SLOTS;
    float acc[8] = {0, 0, 0, 0, 0, 0, 0, 0};
    float den = 0.f;
    for (int k = 0; k < deg; k += 32) {
        // ---- batched independent loads (MLP) ----
        uint4 r[4];
        bool valid[4];
#pragma unroll
        for (int j = 0; j < 4; j++) {
            int idx = k + lane + j * 8;
            valid[j] = idx < deg;
            int ci = min(idx, SLOTS - 1);
            int s = valid[j] ? __float_as_int(__ldg(&g_pair[beg + ci]).x) : 0;
            r[j] = __ldg((const uint4*)&g_h2[s * 8]);
        }
        // ---- sequential unpack/dot/accumulate (one row live at a time) ----
#pragma unroll
        for (int j = 0; j < 4; j++) {
            float2 fa = __half22float2(*(__half2*)&r[j].x);
            float2 fb = __half22float2(*(__half2*)&r[j].y);
            float2 fc = __half22float2(*(__half2*)&r[j].z);
            float2 fd = __half22float2(*(__half2*)&r[j].w);
            float dot = fa.x * att[0];
            dot = fmaf(fa.y, att[1], dot);
            dot = fmaf(fb.x, att[2], dot);
            dot = fmaf(fb.y, att[3], dot);
            dot = fmaf(fc.x, att[4], dot);
            dot = fmaf(fc.y, att[5], dot);
            dot = fmaf(fd.x, att[6], dot);
            dot = fmaf(fd.y, att[7], dot);
            float w = valid[j] ? __expf(lrelu(dot + ad)) : 0.f;
            acc[0] = fmaf(w, fa.x, acc[0]);
            acc[1] = fmaf(w, fa.y, acc[1]);
            acc[2] = fmaf(w, fb.x, acc[2]);
            acc[3] = fmaf(w, fb.y, acc[3]);
            acc[4] = fmaf(w, fc.x, acc[4]);
            acc[5] = fmaf(w, fc.y, acc[5]);
            acc[6] = fmaf(w, fd.x, acc[6]);
            acc[7] = fmaf(w, fd.y, acc[7]);
            den += w;
        }
    }
#pragma unroll
    for (int o = 4; o > 0; o >>= 1) {
#pragma unroll
        for (int c = 0; c < 8; c++) acc[c] += __shfl_xor_sync(0xffffffffu, acc[c], o);
        den += __shfl_xor_sync(0xffffffffu, den, o);
    }
    if (active && lane == 0) {
        g_cursor[gid] = 0;  // restore launch invariant for next call's scatter
        uint4 rh = *(const uint4*)&g_h2[gid * 8];
        float2 ha = __half22float2(*(__half2*)&rh.x);
        float2 hb = __half22float2(*(__half2*)&rh.y);
        float2 hc = __half22float2(*(__half2*)&rh.z);
        float2 hd2 = __half22float2(*(__half2*)&rh.w);
        float hd[8] = {ha.x, ha.y, hb.x, hb.y, hc.x, hc.y, hd2.x, hd2.y};
        float w = __expf(lrelu(g_as2[gid] + ad));  // self-loop
        float inv = 1.f / (den + w + 1e-16f);
        float o[8];
#pragma unroll
        for (int c = 0; c < 8; c++)
            o[c] = fmaf(acc[c] + w * hd[c], inv, b2[c]);
        int b = batch[gid];
        atomicAdd((float4*)&g_gsum[b * 8], make_float4(o[0], o[1], o[2], o[3]));
        atomicAdd((float4*)&g_gsum[b * 8 + 4], make_float4(o[4], o[5], o[6], o[7]));
        atomicAdd(&g_gcnt[b], 1.f);
    }
}

// -------- pooled -> linear -> log_softmax (re-zeroes pool buffers) --------
__global__ void final_k(const float* __restrict__ lw, const float* __restrict__ lb,
                        float* __restrict__ out, int G) {
    int g = blockIdx.x * blockDim.x + threadIdx.x;
    if (g >= G) return;
    float inv = 1.f / fmaxf(g_gcnt[g], 1.f);
    float p[8];
#pragma unroll
    for (int c = 0; c < 8; c++) p[c] = g_gsum[g * 8 + c] * inv;
    // restore launch invariant for next call's gather2
    *(float4*)&g_gsum[g * 8]     = make_float4(0.f, 0.f, 0.f, 0.f);
    *(float4*)&g_gsum[g * 8 + 4] = make_float4(0.f, 0.f, 0.f, 0.f);
    g_gcnt[g] = 0.f;
    float l[10];
    float m = -1e30f;
#pragma unroll
    for (int o = 0; o < 10; o++) {
        float a = lb[o];
#pragma unroll
        for (int c = 0; c < 8; c++) a = fmaf(p[c], lw[c * 10 + o], a);
        l[o] = a;
        m = fmaxf(m, a);
    }
    float s = 0.f;
#pragma unroll
    for (int o = 0; o < 10; o++) s += expf(l[o] - m);
    float lse = m + logf(s);
#pragma unroll
    for (int o = 0; o < 10; o++) out[g * 10 + o] = l[o] - lse;
}

// ---------------- launch ----------------
extern "C" void kernel_launch(void* const* d_in, const int* in_sizes, int n_in,
                              void* d_out, int out_size) {
    const float* x   = (const float*)d_in[0];
    const int*   ei  = (const int*)d_in[1];
    const int*   bat = (const int*)d_in[2];
    const float* W1  = (const float*)d_in[4];
    const float* as1 = (const float*)d_in[5];
    const float* ad1 = (const float*)d_in[6];
    const float* b1  = (const float*)d_in[7];
    const float* W2  = (const float*)d_in[8];
    const float* as2 = (const float*)d_in[9];
    const float* ad2 = (const float*)d_in[10];
    const float* b2  = (const float*)d_in[11];
    const float* lw  = (const float*)d_in[12];
    const float* lb  = (const float*)d_in[13];

    int N = in_sizes[0];
    int E = in_sizes[1] / 2;
    int G = out_size / 10;
    float* out = (float*)d_out;

    scatter_k<<<(E / 16 + 255) / 256, 256>>>(ei, x, E);           // idx 0
    gather1<<<(N * 16 + 255) / 256, 256>>>(x, W1, as1, ad1, N);   // idx 1
    node1<<<(N + 255) / 256, 256>>>(W1, b1, W2, as2, ad2, N);     // idx 2
    gather2<<<(N * 8 + 255) / 256, 256>>>(bat, b2, as2, N);       // idx 3 (profiled)
    final_k<<<(G + 127) / 128, 128>>>(lw, lb, out, G);            // idx 4
}